// round 15
// baseline (speedup 1.0000x reference)
#include <cuda_runtime.h>
#include <cstdint>

// instant-ngp HashEncoder forward: D=3, L=16, C=2, base=16, scale=2, 2^19 hashmap.
// R14: persistent grid + level-0 table cached in SMEM.
//  - level 0 (incl. unclamped-corner overflow, 4369 float2 = ~35KB) staged in
//    shared memory ONCE per block; its gathers use the LDS crossbar and leave
//    the L1tex wavefront queue (~6% of gather wavefronts removed).
//  - levels >=1: unchanged R10 fast path (even-ix float4 pair-merge).
//  - persistent 888-block grid, grid-stride over B*16 work items.

#define PRIME_Y 2654435761u
#define PRIME_Z 805459861u
#define HASH_MASK 524287u  // 2^19 - 1
#define L0_ENTRIES 4370    // max dense-l0 index 4368 (+pad)

__device__ __forceinline__ void stg_cs_f2(float* p, float2 v) {
    asm volatile("st.global.cs.v2.f32 [%0], {%1,%2};"
                 :: "l"(p), "f"(v.x), "f"(v.y) : "memory");
}

__global__ __launch_bounds__(256) void hashenc_fwd(
    const float* __restrict__ inp,   // [B, 3]
    const float* __restrict__ emb,   // [TOTAL_PARAMS * 2] scalar float view
    float* __restrict__ out,         // [B, 32]
    int B)
{
    __shared__ __align__(16) float2 s0[L0_ENTRIES];

    // stage level-0 table (coalesced, once per block)
    const float2* emb2 = (const float2*)emb;
    for (int i = threadIdx.x; i < L0_ENTRIES; i += blockDim.x)
        s0[i] = __ldg(emb2 + i);
    __syncthreads();

    const long long total = (long long)B * 16;
    const long long stride = (long long)gridDim.x * blockDim.x;

    for (long long w = (long long)blockIdx.x * blockDim.x + threadIdx.x;
         w < total; w += stride) {
        const int p = (int)(w >> 4);   // point index
        const int l = (int)(w & 15);   // level index

        const float x = (__ldg(inp + 3 * p + 0) + 1.0f) * 0.5f;
        const float y = (__ldg(inp + 3 * p + 1) + 1.0f) * 0.5f;
        const float z = (__ldg(inp + 3 * p + 2) + 1.0f) * 0.5f;

        const uint32_t res = 16u << l;
        const float scale = (float)res - 1.0f;

        const float px = x * scale + 0.5f;
        const float py = y * scale + 0.5f;
        const float pz = z * scale + 0.5f;

        const float gx = floorf(px);
        const float gy = floorf(py);
        const float gz = floorf(pz);

        const float tx = px - gx;
        const float ty = py - gy;
        const float tz = pz - gz;

        const uint32_t ix = (uint32_t)gx;
        const uint32_t iy = (uint32_t)gy;
        const uint32_t iz = (uint32_t)gz;

        const float wy[2] = {1.0f - ty, ty};
        const float wz[2] = {1.0f - tz, tz};

        float sx = 0.0f, sy = 0.0f;

        if (l == 0) {
            // dense res=16 from SMEM (LDS pipe, not L1tex)
            const uint32_t cy0 = iy * 16u,  cy1 = cy0 + 16u;
            const uint32_t cz0 = iz * 256u, cz1 = cz0 + 256u;
#pragma unroll
            for (int c = 0; c < 4; ++c) {
                const uint32_t i0 = ix + ((c & 1) ? cy1 : cy0) + ((c & 2) ? cz1 : cz0);
                const float2 g0 = s0[i0];
                const float2 g1 = s0[i0 + 1u];
                const float wyz = wy[c & 1] * wz[(c >> 1) & 1];
                const float w1 = tx * wyz;
                const float w0 = wyz - w1;
                sx = fmaf(w0, g0.x, fmaf(w1, g1.x, sx));
                sy = fmaf(w0, g0.y, fmaf(w1, g1.y, sy));
            }
        } else {
            const bool dense = (l < 3);
            uint32_t off;
            if (dense) off = (l == 1) ? 4096u : 36864u;
            else       off = 299008u + (uint32_t)(l - 3) * 524288u;

            const uint32_t dy = dense ? res       : PRIME_Y;
            const uint32_t dz = dense ? res * res : PRIME_Z;
            const uint32_t cy0 = iy * dy, cy1 = cy0 + dy;
            const uint32_t cz0 = iz * dz, cz1 = cz0 + dz;

            const float* lvl = emb + 2u * off;

            if ((ix & 1u) == 0u) {
                // merged: both x-corners in one 16B-aligned float4
#pragma unroll
                for (int c = 0; c < 4; ++c) {
                    const uint32_t my = (c & 1) ? cy1 : cy0;
                    const uint32_t mz = (c & 2) ? cz1 : cz0;
                    const uint32_t i0 = dense ? (ix + my + mz)
                                              : ((ix ^ my ^ mz) & HASH_MASK);
                    const uint32_t base = i0 & ~1u;
                    const uint32_t sw = i0 & 1u;   // 0 on dense path

                    const float4 g4 = __ldg((const float4*)(lvl + 2u * base));
                    float2 g0, g1;
                    if (sw) { g0 = make_float2(g4.z, g4.w); g1 = make_float2(g4.x, g4.y); }
                    else    { g0 = make_float2(g4.x, g4.y); g1 = make_float2(g4.z, g4.w); }

                    const float wyz = wy[c & 1] * wz[(c >> 1) & 1];
                    const float w1 = tx * wyz;
                    const float w0 = wyz - w1;
                    sx = fmaf(w0, g0.x, fmaf(w1, g1.x, sx));
                    sy = fmaf(w0, g0.y, fmaf(w1, g1.y, sy));
                }
            } else {
                const uint32_t ix1 = ix + 1u;
#pragma unroll
                for (int c = 0; c < 4; ++c) {
                    const uint32_t my = (c & 1) ? cy1 : cy0;
                    const uint32_t mz = (c & 2) ? cz1 : cz0;
                    uint32_t i0, i1;
                    if (dense) {
                        i0 = ix + my + mz;
                        i1 = i0 + 1u;
                    } else {
                        const uint32_t m = my ^ mz;
                        i0 = (ix  ^ m) & HASH_MASK;
                        i1 = (ix1 ^ m) & HASH_MASK;
                    }
                    const float2 g0 = __ldg((const float2*)(lvl + 2u * i0));
                    const float2 g1 = __ldg((const float2*)(lvl + 2u * i1));

                    const float wyz = wy[c & 1] * wz[(c >> 1) & 1];
                    const float w1 = tx * wyz;
                    const float w0 = wyz - w1;
                    sx = fmaf(w0, g0.x, fmaf(w1, g1.x, sx));
                    sy = fmaf(w0, g0.y, fmaf(w1, g1.y, sy));
                }
            }
        }

        // fully-coalesced 8B store (warp covers 2 points x 128B)
        stg_cs_f2((float*)out + (size_t)w * 2, make_float2(sx, sy));
    }
}

extern "C" void kernel_launch(void* const* d_in, const int* in_sizes, int n_in,
                              void* d_out, int out_size)
{
    const float* p0 = (const float*)d_in[0];
    const float* p1 = (const float*)d_in[1];
    const float* inp;
    const float* emb;
    int B;
    if (in_sizes[0] < in_sizes[1]) {
        inp = p0; emb = p1; B = in_sizes[0] / 3;
    } else {
        inp = p1; emb = p0; B = in_sizes[1] / 3;
    }
    const int threads = 256;
    const int blocks = 148 * 6;   // persistent grid, grid-stride loop
    hashenc_fwd<<<blocks, threads>>>(inp, emb, (float*)d_out, B);
}

// round 17
// speedup vs baseline: 2.1756x; 2.1756x over previous
#include <cuda_runtime.h>
#include <cstdint>

// instant-ngp HashEncoder forward: D=3, L=16, C=2, base=16, scale=2, 2^19 hashmap.
// FINAL (= R10, measured 291.1us, L1tex wavefront-floor bound):
//  - 16 threads per point, one level per thread (flat mapping -> ptxas
//    front-batches all gathers, high MLP, minimal live state: 32 regs)
//  - even-ix corner pairs: both x-corners fetched with ONE 16B-aligned float4
//    (one L1 wavefront instead of two; spread identity i0^i1 = ix^(ix+1))
//  - store: one coalesced 8B .cs store per thread (2 points x 128B per warp),
//    streaming so the 128MB output doesn't thrash L2
// Excursions tested and rejected: LDG.256 merges (wavefront cost is per-16B
// per lane), predicated single-stream (issue wasn't binding), 2 points/thread,
// occupancy 8/SM (L2 thrash), cache policies (neutral), smem level-0 staging
// in a persistent grid (destroyed load batching, 2.2x regression).

#define PRIME_Y 2654435761u
#define PRIME_Z 805459861u
#define HASH_MASK 524287u  // 2^19 - 1

__device__ __forceinline__ void stg_cs_f2(float* p, float2 v) {
    asm volatile("st.global.cs.v2.f32 [%0], {%1,%2};"
                 :: "l"(p), "f"(v.x), "f"(v.y) : "memory");
}

__global__ __launch_bounds__(256) void hashenc_fwd(
    const float* __restrict__ inp,   // [B, 3]
    const float* __restrict__ emb,   // [TOTAL_PARAMS * 2] scalar float view
    float* __restrict__ out,         // [B, 32]
    int B)
{
    const int gtid = blockIdx.x * blockDim.x + threadIdx.x;
    const int p = gtid >> 4;       // point index
    const int l = gtid & 15;       // level index
    if (p >= B) return;

    // 16 lanes share a point -> broadcast loads
    const float x = (__ldg(inp + 3 * p + 0) + 1.0f) * 0.5f;
    const float y = (__ldg(inp + 3 * p + 1) + 1.0f) * 0.5f;
    const float z = (__ldg(inp + 3 * p + 2) + 1.0f) * 0.5f;

    const uint32_t res = 16u << l;
    const float scale = (float)res - 1.0f;
    const bool dense = (l < 3);

    // level offset in float2 elements:
    // l=0:0, l=1:4096, l=2:36864, l>=3: 299008 + (l-3)*524288
    uint32_t off;
    if (dense) off = (l == 0) ? 0u : (l == 1) ? 4096u : 36864u;
    else       off = 299008u + (uint32_t)(l - 3) * 524288u;

    const float px = x * scale + 0.5f;
    const float py = y * scale + 0.5f;
    const float pz = z * scale + 0.5f;

    const float gx = floorf(px);
    const float gy = floorf(py);
    const float gz = floorf(pz);

    const float tx = px - gx;
    const float ty = py - gy;
    const float tz = pz - gz;

    const uint32_t ix = (uint32_t)gx;
    const uint32_t iy = (uint32_t)gy;
    const uint32_t iz = (uint32_t)gz;

    // per-dim corner components, branchless dense/hashed select
    const uint32_t dy = dense ? res       : PRIME_Y;
    const uint32_t dz = dense ? res * res : PRIME_Z;
    const uint32_t cy0 = iy * dy, cy1 = cy0 + dy;
    const uint32_t cz0 = iz * dz, cz1 = cz0 + dz;

    const float wy[2] = {1.0f - ty, ty};
    const float wz[2] = {1.0f - tz, tz};

    const float* lvl = emb + 2u * off;

    float sx = 0.0f, sy = 0.0f;

    if ((ix & 1u) == 0u) {
        // merged: both x-corners live in one 16B-aligned float4 (one wavefront)
#pragma unroll
        for (int c = 0; c < 4; ++c) {
            const uint32_t my = (c & 1) ? cy1 : cy0;
            const uint32_t mz = (c & 2) ? cz1 : cz0;
            const uint32_t i0 = dense ? (ix + my + mz)
                                      : ((ix ^ my ^ mz) & HASH_MASK);
            const uint32_t base = i0 & ~1u;
            const uint32_t sw = i0 & 1u;   // 0 on dense path (all terms even)

            const float4 g4 = __ldg((const float4*)(lvl + 2u * base));
            float2 g0, g1;
            if (sw) { g0 = make_float2(g4.z, g4.w); g1 = make_float2(g4.x, g4.y); }
            else    { g0 = make_float2(g4.x, g4.y); g1 = make_float2(g4.z, g4.w); }

            const float wyz = wy[c & 1] * wz[(c >> 1) & 1];
            const float w1 = tx * wyz;
            const float w0 = wyz - w1;
            sx = fmaf(w0, g0.x, fmaf(w1, g1.x, sx));
            sy = fmaf(w0, g0.y, fmaf(w1, g1.y, sy));
        }
    } else {
        const uint32_t ix1 = ix + 1u;
#pragma unroll
        for (int c = 0; c < 4; ++c) {
            const uint32_t my = (c & 1) ? cy1 : cy0;
            const uint32_t mz = (c & 2) ? cz1 : cz0;
            uint32_t i0, i1;
            if (dense) {
                i0 = ix + my + mz;
                i1 = i0 + 1u;
            } else {
                const uint32_t m = my ^ mz;
                i0 = (ix  ^ m) & HASH_MASK;
                i1 = (ix1 ^ m) & HASH_MASK;
            }
            const float2 g0 = __ldg((const float2*)(lvl + 2u * i0));
            const float2 g1 = __ldg((const float2*)(lvl + 2u * i1));

            const float wyz = wy[c & 1] * wz[(c >> 1) & 1];
            const float w1 = tx * wyz;
            const float w0 = wyz - w1;
            sx = fmaf(w0, g0.x, fmaf(w1, g1.x, sx));
            sy = fmaf(w0, g0.y, fmaf(w1, g1.y, sy));
        }
    }

    // one fully-coalesced 8B store per thread: warp writes 2 points x 128B
    stg_cs_f2((float*)out + (size_t)gtid * 2, make_float2(sx, sy));
}

extern "C" void kernel_launch(void* const* d_in, const int* in_sizes, int n_in,
                              void* d_out, int out_size)
{
    const float* p0 = (const float*)d_in[0];
    const float* p1 = (const float*)d_in[1];
    const float* inp;
    const float* emb;
    int B;
    if (in_sizes[0] < in_sizes[1]) {
        inp = p0; emb = p1; B = in_sizes[0] / 3;
    } else {
        inp = p1; emb = p0; B = in_sizes[1] / 3;
    }
    const int threads = 256;
    const long long total = (long long)B * 16;
    const int blocks = (int)((total + threads - 1) / threads);
    hashenc_fwd<<<blocks, threads>>>(inp, emb, (float*)d_out, B);
}